// round 7
// baseline (speedup 1.0000x reference)
#include <cuda_runtime.h>
#include <cuda_bf16.h>
#include <cstdint>

#define NN 512

// ---------------- scratch (no allocations allowed) ----------------
__device__ float g_A[NN * 256];
__device__ float g_B[NN * 256];
__device__ float g_S2a[NN * 256];
__device__ float g_S2b[NN * 256];
// Wf2 split into bf16 hi/lo, chunked layout [kc][n][64]
__device__ uint4 g_Whi4[8192];
__device__ uint4 g_Wlo4[8192];

// ================= helpers =================
__device__ __forceinline__ uint32_t smem_u32(const void* p) {
    uint32_t a;
    asm("{ .reg .u64 t; cvta.to.shared.u64 t, %1; cvt.u32.u64 %0, t; }" : "=r"(a) : "l"(p));
    return a;
}

__device__ __forceinline__ void ldsm4(uint32_t (&r)[4], uint32_t addr) {
    asm volatile("ldmatrix.sync.aligned.m8n8.x4.shared.b16 {%0,%1,%2,%3}, [%4];"
        : "=r"(r[0]), "=r"(r[1]), "=r"(r[2]), "=r"(r[3]) : "r"(addr));
}

__device__ __forceinline__ void mma16816(float (&d)[4], const uint32_t (&a)[4],
                                         uint32_t b0, uint32_t b1) {
    asm volatile(
        "mma.sync.aligned.m16n8k16.row.col.f32.bf16.bf16.f32 "
        "{%0,%1,%2,%3}, {%4,%5,%6,%7}, {%8,%9}, {%0,%1,%2,%3};"
        : "+f"(d[0]), "+f"(d[1]), "+f"(d[2]), "+f"(d[3])
        : "r"(a[0]), "r"(a[1]), "r"(a[2]), "r"(a[3]), "r"(b0), "r"(b1));
}

__device__ __forceinline__ uint32_t pack_rn2(float f0, float f1) {
    uint32_t r; asm("cvt.rn.bf16x2.f32 %0, %1, %2;" : "=r"(r) : "f"(f1), "f"(f0));
    return r;
}

#define CP_ASYNC16(dst, src) \
    asm volatile("cp.async.cg.shared.global [%0], [%1], 16;" :: "r"(dst), "l"(src))
#define CP_COMMIT() asm volatile("cp.async.commit_group;" ::: "memory")
#define CP_WAIT0()  asm volatile("cp.async.wait_group 0;"  ::: "memory")

// ================= pair kernel smem layout (byte offsets) =================
#define OFF_WHI 0u         // 2 x 32768
#define OFF_WLO 65536u     // 2 x 32768
#define OFF_RAW 131072u    // 2 x 32768 (raw A fp32, linear [row][kseg])
#define OFF_AHI 196608u    // 16384 (split hi, swizzled)
#define OFF_ALO 212992u    // 16384
#define OFF_BB  229376u    // 1024
#define OFF_B2  230400u    // 1024
#define PAIR_DYN_SMEM (231424u + 128u)

// ---------------- pairwise HMMA kernel (unchanged from round 6) ----------------
__global__ __launch_bounds__(256, 1) void pair_mma_kernel(
    const float* __restrict__ A, const float* __restrict__ Bm,
    const float* __restrict__ bf1, const float* __restrict__ bf2,
    float* __restrict__ S2a, float* __restrict__ S2b)
{
    extern __shared__ __align__(16) char smraw[];
    const uint32_t raw0 = smem_u32(smraw);
    const uint32_t sb = (raw0 + 127u) & ~127u;
    char* smp = smraw + (sb - raw0);

    const int j = blockIdx.x;
    const int half = blockIdx.y;
    const int t = threadIdx.x;
    const int lane = t & 31;
    const int w = t >> 5;
    const int wm = w >> 2;
    const int wn = w & 3;

    float* sBB = (float*)(smp + OFF_BB);
    float* sB2 = (float*)(smp + OFF_B2);

    sBB[t] = Bm[j * 256 + t] + bf1[t];
    sB2[t] = bf2[t];

    const uint32_t lx = (uint32_t)(lane & 7) * 16u;
    const uint32_t rowOff = (uint32_t)(lane & 15) * 128u;
    const uint32_t segOff = (uint32_t)(lane >> 4) * 16u;
    const uint32_t wmOff = (uint32_t)(wm * 64) * 128u + rowOff;
    const uint32_t wnOff = (uint32_t)(wn * 64) * 128u + rowOff;

    float s[16];
#pragma unroll
    for (int q = 0; q < 16; q++) s[q] = 0.f;

    float acc[4][8][4];
#pragma unroll
    for (int mt = 0; mt < 4; mt++)
#pragma unroll
        for (int nt = 0; nt < 8; nt++)
#pragma unroll
            for (int e = 0; e < 4; e++) acc[mt][nt][e] = 0.f;

#define STAGE_W_ASYNC(kc_, wb_) do { \
        const uint32_t wHiA = sb + OFF_WHI + (uint32_t)(wb_) * 32768u; \
        const uint32_t wLoA = sb + OFF_WLO + (uint32_t)(wb_) * 32768u; \
        const uint4* srcH = g_Whi4 + (kc_) * 2048; \
        const uint4* srcL = g_Wlo4 + (kc_) * 2048; \
        _Pragma("unroll") \
        for (int r = 0; r < 8; r++) { \
            const int li = r * 256 + t; \
            const int n_ = li >> 3, seg_ = li & 7; \
            const uint32_t sw = ((uint32_t)(n_ * 128 + seg_ * 16)) ^ ((uint32_t)(n_ & 7) * 16u); \
            CP_ASYNC16(wHiA + sw, (const void*)(srcH + li)); \
            CP_ASYNC16(wLoA + sw, (const void*)(srcL + li)); \
        } \
    } while (0)

#define STAGE_A_ASYNC(it_, kc_, rb_) do { \
        const uint32_t rawA = sb + OFF_RAW + (uint32_t)(rb_) * 32768u; \
        const float* srcA = A + ((it_) * 128) * 256 + (kc_) * 64; \
        _Pragma("unroll") \
        for (int r = 0; r < 8; r++) { \
            const int li = r * 256 + t; \
            const int row_ = li >> 4, seg_ = li & 15; \
            CP_ASYNC16(rawA + (uint32_t)li * 16u, (const void*)(srcA + row_ * 256 + seg_ * 4)); \
        } \
    } while (0)

#define CONVERT_A(kc_, rb_) do { \
        const float* rawp = (const float*)(smp + OFF_RAW + (uint32_t)(rb_) * 32768u); \
        char* aHi = smp + OFF_AHI; \
        char* aLo = smp + OFF_ALO; \
        _Pragma("unroll") \
        for (int r = 0; r < 8; r++) { \
            const int li = r * 256 + t; \
            const int row_ = li >> 4, seg_ = li & 15; \
            float4 v = *(const float4*)(rawp + li * 4); \
            float4 bbv = *(const float4*)(sBB + (kc_) * 64 + seg_ * 4); \
            float f0 = fmaxf(v.x + bbv.x, 0.f), f1 = fmaxf(v.y + bbv.y, 0.f); \
            float f2 = fmaxf(v.z + bbv.z, 0.f), f3 = fmaxf(v.w + bbv.w, 0.f); \
            uint2 hp, lp; \
            hp.x = pack_rn2(f0, f1); hp.y = pack_rn2(f2, f3); \
            lp.x = pack_rn2(f0 - __uint_as_float(hp.x << 16), \
                            f1 - __uint_as_float(hp.x & 0xFFFF0000u)); \
            lp.y = pack_rn2(f2 - __uint_as_float(hp.y << 16), \
                            f3 - __uint_as_float(hp.y & 0xFFFF0000u)); \
            const uint32_t off_ = (uint32_t)(row_ * 128 + seg_ * 8); \
            const uint32_t sw = off_ ^ ((uint32_t)(row_ & 7) * 16u); \
            *(uint2*)(aHi + sw) = hp; \
            *(uint2*)(aLo + sw) = lp; \
        } \
    } while (0)

    STAGE_W_ASYNC(0, 0);
    STAGE_A_ASYNC(half * 2, 0, 0);
    CP_COMMIT();
    __syncthreads();
    CP_WAIT0();
    CONVERT_A(0, 0);
    __syncthreads();

#pragma unroll 1
    for (int c = 0; c < 8; c++) {
        const int b = c & 1;

        if (c < 7) {
            STAGE_W_ASYNC((c + 1) & 3, b ^ 1);
            STAGE_A_ASYNC(half * 2 + ((c + 1) >> 2), (c + 1) & 3, b ^ 1);
            CP_COMMIT();
        }

        {
            const uint32_t aRowHi = sb + OFF_AHI + wmOff;
            const uint32_t aRowLo = sb + OFF_ALO + wmOff;
            const uint32_t wRowHi = sb + OFF_WHI + (uint32_t)b * 32768u + wnOff;
            const uint32_t wRowLo = sb + OFF_WLO + (uint32_t)b * 32768u + wnOff;
#pragma unroll
            for (int ks = 0; ks < 4; ks++) {
                const uint32_t kx = ((uint32_t)(ks * 32) + segOff) ^ lx;
                uint32_t aH[4][4], aL[4][4], wf[4][4];
#pragma unroll
                for (int mt = 0; mt < 4; mt++) ldsm4(aH[mt], aRowHi + mt * 2048 + kx);
#pragma unroll
                for (int np = 0; np < 4; np++) ldsm4(wf[np], wRowHi + np * 2048 + kx);
#pragma unroll
                for (int mt = 0; mt < 4; mt++)
#pragma unroll
                    for (int np = 0; np < 4; np++) {
                        mma16816(acc[mt][2 * np],     aH[mt], wf[np][0], wf[np][2]);
                        mma16816(acc[mt][2 * np + 1], aH[mt], wf[np][1], wf[np][3]);
                    }
#pragma unroll
                for (int mt = 0; mt < 4; mt++) ldsm4(aL[mt], aRowLo + mt * 2048 + kx);
#pragma unroll
                for (int mt = 0; mt < 4; mt++)
#pragma unroll
                    for (int np = 0; np < 4; np++) {
                        mma16816(acc[mt][2 * np],     aL[mt], wf[np][0], wf[np][2]);
                        mma16816(acc[mt][2 * np + 1], aL[mt], wf[np][1], wf[np][3]);
                    }
#pragma unroll
                for (int np = 0; np < 4; np++) ldsm4(wf[np], wRowLo + np * 2048 + kx);
#pragma unroll
                for (int mt = 0; mt < 4; mt++)
#pragma unroll
                    for (int np = 0; np < 4; np++) {
                        mma16816(acc[mt][2 * np],     aH[mt], wf[np][0], wf[np][2]);
                        mma16816(acc[mt][2 * np + 1], aH[mt], wf[np][1], wf[np][3]);
                    }
            }
        }

        __syncthreads();

        if (c < 7) {
            CP_WAIT0();
            CONVERT_A((c + 1) & 3, b ^ 1);
        }

        if ((c & 3) == 3) {
#pragma unroll
            for (int nt = 0; nt < 8; nt++) {
                const int col = wn * 64 + nt * 8 + (lane & 3) * 2;
                const float b20 = sB2[col], b21 = sB2[col + 1];
                float t0 = 0.f, t1 = 0.f;
#pragma unroll
                for (int mt = 0; mt < 4; mt++) {
                    t0 += fmaxf(acc[mt][nt][0] + b20, 0.f) + fmaxf(acc[mt][nt][2] + b20, 0.f);
                    t1 += fmaxf(acc[mt][nt][1] + b21, 0.f) + fmaxf(acc[mt][nt][3] + b21, 0.f);
                    acc[mt][nt][0] = 0.f; acc[mt][nt][1] = 0.f;
                    acc[mt][nt][2] = 0.f; acc[mt][nt][3] = 0.f;
                }
                s[nt * 2]     += t0;
                s[nt * 2 + 1] += t1;
            }
        }

        __syncthreads();
    }

#pragma unroll
    for (int q = 0; q < 16; q++) {
        s[q] += __shfl_xor_sync(0xFFFFFFFFu, s[q], 4);
        s[q] += __shfl_xor_sync(0xFFFFFFFFu, s[q], 8);
        s[q] += __shfl_xor_sync(0xFFFFFFFFu, s[q], 16);
    }
    float* sRED = (float*)(smp + OFF_RAW);
    if (lane < 4) {
#pragma unroll
        for (int nt = 0; nt < 8; nt++) {
            const int col = wn * 64 + nt * 8 + lane * 2;
            sRED[wm * 256 + col]     = s[nt * 2];
            sRED[wm * 256 + col + 1] = s[nt * 2 + 1];
        }
    }
    __syncthreads();
    float* dst = half ? S2b : S2a;
    dst[j * 256 + t] = sRED[t] + sRED[256 + t];
}

// ---------------- fused prep: Wf2 split (bid<256) + A/B projection (bid>=256) ----------------
__global__ __launch_bounds__(256) void prep_ab_kernel(
    const float* __restrict__ hid, const float* __restrict__ Wf1,
    const float* __restrict__ Wf2)
{
    __shared__ float sX[32][34];
    __shared__ float sW[32][34];
    const int bid = blockIdx.x;
    const int t = threadIdx.x;

    if (bid < 256) {
        // Wf2 -> bf16 hi/lo chunked prep
        const int idx = bid * 256 + t;
        const int n = idx >> 8, k = idx & 255;
        const float v = Wf2[idx];
        const __nv_bfloat16 hb = __float2bfloat16(v);
        const float lf = v - __bfloat162float(hb);
        const int o = (k >> 6) * 16384 + n * 64 + (k & 63);
        ((__nv_bfloat16*)g_Whi4)[o] = hb;
        ((__nv_bfloat16*)g_Wlo4)[o] = __float2bfloat16(lf);
        return;
    }

    // A/B projection: b = bid-256 in [0,256): z = b>>7, m-tile = (b&127)>>3, n-tile = b&7
    const int b = bid - 256;
    const int z = b >> 7;
    const int rem = b & 127;
    const int m0 = (rem >> 3) * 32;
    const int n0 = (rem & 7) * 32;
    const float* W = Wf1 + z * 128;
    float* C = z ? g_B : g_A;

    const int lm = t >> 3;
    const int lk = (t & 7) * 4;
    const int tm = (t >> 4) * 2;
    const int tn = (t & 15) * 2;

    float a00 = 0.f, a01 = 0.f, a10 = 0.f, a11 = 0.f;
    float4 xv = *(const float4*)(hid + (m0 + lm) * 128 + lk);
    float4 wv = *(const float4*)(W + (n0 + lm) * 256 + lk);

    for (int c = 0; c < 4; c++) {
        __syncthreads();
        sX[lk + 0][lm] = xv.x; sX[lk + 1][lm] = xv.y;
        sX[lk + 2][lm] = xv.z; sX[lk + 3][lm] = xv.w;
        sW[lk + 0][lm] = wv.x; sW[lk + 1][lm] = wv.y;
        sW[lk + 2][lm] = wv.z; sW[lk + 3][lm] = wv.w;
        __syncthreads();
        if (c < 3) {
            const int ko = (c + 1) * 32 + lk;
            xv = *(const float4*)(hid + (m0 + lm) * 128 + ko);
            wv = *(const float4*)(W + (n0 + lm) * 256 + ko);
        }
#pragma unroll
        for (int kk = 0; kk < 32; kk++) {
            float2 avv = *(const float2*)&sX[kk][tm];
            float2 bvv = *(const float2*)&sW[kk][tn];
            a00 = fmaf(avv.x, bvv.x, a00);
            a01 = fmaf(avv.x, bvv.y, a01);
            a10 = fmaf(avv.y, bvv.x, a10);
            a11 = fmaf(avv.y, bvv.y, a11);
        }
    }
    const int m = m0 + tm, n = n0 + tn;
    C[m * 256 + n] = a00;       C[m * 256 + n + 1] = a01;
    C[(m + 1) * 256 + n] = a10; C[(m + 1) * 256 + n + 1] = a11;
}

// ---------------- fused tail: summ -> g-MLP -> LSTM -> o-MLP, row-parallel ----------------
// 128 CTAs x 4 rows; layers separated by __syncthreads; intermediates ping-pong in smem.
__device__ __forceinline__ float4 gemv4(
    const float* __restrict__ x0, const float* __restrict__ x1,
    const float* __restrict__ x2, const float* __restrict__ x3,
    const float* __restrict__ wrow, int K)
{
    float a0 = 0.f, a1 = 0.f, a2 = 0.f, a3 = 0.f;
#pragma unroll 4
    for (int k = 0; k < K; k += 4) {
        const float4 w = *(const float4*)(wrow + k);
        const float4 v0 = *(const float4*)(x0 + k);
        const float4 v1 = *(const float4*)(x1 + k);
        const float4 v2 = *(const float4*)(x2 + k);
        const float4 v3 = *(const float4*)(x3 + k);
        a0 += w.x * v0.x + w.y * v0.y + w.z * v0.z + w.w * v0.w;
        a1 += w.x * v1.x + w.y * v1.y + w.z * v1.z + w.w * v1.w;
        a2 += w.x * v2.x + w.y * v2.y + w.z * v2.z + w.w * v2.w;
        a3 += w.x * v3.x + w.y * v3.y + w.z * v3.z + w.w * v3.w;
    }
    return make_float4(a0, a1, a2, a3);
}

__global__ __launch_bounds__(256) void tail_kernel(
    const float* __restrict__ x,   const float* __restrict__ h0,
    const float* __restrict__ c0,
    const float* __restrict__ Wf3, const float* __restrict__ bf3,
    const float* __restrict__ Wg1, const float* __restrict__ bg1,
    const float* __restrict__ Wg2, const float* __restrict__ bg2,
    const float* __restrict__ Wg3, const float* __restrict__ bg3,
    const float* __restrict__ W_ih, const float* __restrict__ W_hh,
    const float* __restrict__ b_ih, const float* __restrict__ b_hh,
    const float* __restrict__ Wo1, const float* __restrict__ bo1,
    const float* __restrict__ Wo2, const float* __restrict__ bo2,
    float* __restrict__ out)
{
    __shared__ float Xa[4][512];
    __shared__ float Xb[4][512];
    const int t = threadIdx.x;
    const int r0 = blockIdx.x * 4;

    // stage 0: Xa <- S2a + S2b  (K=256 input)
#pragma unroll
    for (int r = 0; r < 4; r++)
        Xa[r][t] = g_S2a[(r0 + r) * 256 + t] + g_S2b[(r0 + r) * 256 + t];
    __syncthreads();

    // stage 1: Xb <- [x | summ];  summ = Xa @ Wf3^T + 512*bf3
    if (t < 128) {
        float4 a = gemv4(Xa[0], Xa[1], Xa[2], Xa[3], Wf3 + t * 256, 256);
        const float bias = 512.f * bf3[t];
        Xb[0][128 + t] = a.x + bias; Xb[1][128 + t] = a.y + bias;
        Xb[2][128 + t] = a.z + bias; Xb[3][128 + t] = a.w + bias;
    } else {
        const int n = t - 128;
#pragma unroll
        for (int r = 0; r < 4; r++) Xb[r][n] = x[(r0 + r) * 128 + n];
    }
    __syncthreads();

    // stage 2: Xa <- g1 = relu(Xb @ Wg1^T + bg1)   (K=256, N=256)
    {
        float4 a = gemv4(Xb[0], Xb[1], Xb[2], Xb[3], Wg1 + t * 256, 256);
        const float bias = bg1[t];
        Xa[0][t] = fmaxf(a.x + bias, 0.f); Xa[1][t] = fmaxf(a.y + bias, 0.f);
        Xa[2][t] = fmaxf(a.z + bias, 0.f); Xa[3][t] = fmaxf(a.w + bias, 0.f);
    }
    __syncthreads();

    // stage 3: Xb <- g2 = relu(Xa @ Wg2^T + bg2)
    {
        float4 a = gemv4(Xa[0], Xa[1], Xa[2], Xa[3], Wg2 + t * 256, 256);
        const float bias = bg2[t];
        Xb[0][t] = fmaxf(a.x + bias, 0.f); Xb[1][t] = fmaxf(a.y + bias, 0.f);
        Xb[2][t] = fmaxf(a.z + bias, 0.f); Xb[3][t] = fmaxf(a.w + bias, 0.f);
    }
    __syncthreads();

    // stage 4: Xa <- [ig | h0];  ig = Xb @ Wg3^T + bg3  (N=128)
    if (t < 128) {
        float4 a = gemv4(Xb[0], Xb[1], Xb[2], Xb[3], Wg3 + t * 256, 256);
        const float bias = bg3[t];
        Xa[0][t] = a.x + bias; Xa[1][t] = a.y + bias;
        Xa[2][t] = a.z + bias; Xa[3][t] = a.w + bias;
    } else {
        const int n = t - 128;
#pragma unroll
        for (int r = 0; r < 4; r++) Xa[r][128 + n] = h0[(r0 + r) * 128 + n];
    }
    __syncthreads();

    // stage 5: Xb <- gates (N=512): ig@W_ih^T + h0@W_hh^T + b_ih + b_hh
#pragma unroll
    for (int q = 0; q < 2; q++) {
        const int n = t + q * 256;
        float4 a = gemv4(Xa[0], Xa[1], Xa[2], Xa[3], W_ih + n * 128, 128);
        float4 bcc = gemv4(Xa[0] + 128, Xa[1] + 128, Xa[2] + 128, Xa[3] + 128,
                           W_hh + n * 128, 128);
        const float bias = b_ih[n] + b_hh[n];
        Xb[0][n] = a.x + bcc.x + bias; Xb[1][n] = a.y + bcc.y + bias;
        Xb[2][n] = a.z + bcc.z + bias; Xb[3][n] = a.w + bcc.w + bias;
    }
    __syncthreads();

    // stage 6: LSTM elementwise; hn -> Xa[r][0..127] + gmem, c -> gmem
#pragma unroll
    for (int q = 0; q < 2; q++) {
        const int item = t + q * 256;       // 0..511 = r*128 + h
        const int r = item >> 7, h = item & 127;
        const float ig = 1.f / (1.f + expf(-Xb[r][h]));
        const float fg = 1.f / (1.f + expf(-Xb[r][128 + h]));
        const float gg = tanhf(Xb[r][256 + h]);
        const float og = 1.f / (1.f + expf(-Xb[r][384 + h]));
        const int gi = (r0 + r) * 128 + h;
        const float c = fg * c0[gi] + ig * gg;
        const float hn = og * tanhf(c);
        Xa[r][h] = hn;
        out[32768 + gi]  = hn;
        out[98304 + gi]  = hn;
        out[163840 + gi] = c;
    }
    __syncthreads();

    // stage 7: Xb <- o1 = relu(hn @ Wo1^T + bo1)  (K=128, N=256)
    {
        float4 a = gemv4(Xa[0], Xa[1], Xa[2], Xa[3], Wo1 + t * 128, 128);
        const float bias = bo1[t];
        Xb[0][t] = fmaxf(a.x + bias, 0.f); Xb[1][t] = fmaxf(a.y + bias, 0.f);
        Xb[2][t] = fmaxf(a.z + bias, 0.f); Xb[3][t] = fmaxf(a.w + bias, 0.f);
    }
    __syncthreads();

    // stage 8: out = o1 @ Wo2^T + bo2  (K=256, N=64)
    if (t < 64) {
        float4 a = gemv4(Xb[0], Xb[1], Xb[2], Xb[3], Wo2 + t * 256, 256);
        const float bias = bo2[t];
        out[(r0 + 0) * 64 + t] = a.x + bias;
        out[(r0 + 1) * 64 + t] = a.y + bias;
        out[(r0 + 2) * 64 + t] = a.z + bias;
        out[(r0 + 3) * 64 + t] = a.w + bias;
    }
}

// ---------------- launch ----------------
extern "C" void kernel_launch(void* const* d_in, const int* in_sizes, int n_in,
                              void* d_out, int out_size)
{
    const float* x    = (const float*)d_in[0];
    const float* hid  = (const float*)d_in[1];
    const float* h0   = (const float*)d_in[2];
    const float* c0   = (const float*)d_in[3];
    const float* Wf1  = (const float*)d_in[4];
    const float* bf1  = (const float*)d_in[5];
    const float* Wf2  = (const float*)d_in[6];
    const float* bf2  = (const float*)d_in[7];
    const float* Wf3  = (const float*)d_in[8];
    const float* bf3  = (const float*)d_in[9];
    const float* Wg1  = (const float*)d_in[10];
    const float* bg1  = (const float*)d_in[11];
    const float* Wg2  = (const float*)d_in[12];
    const float* bg2  = (const float*)d_in[13];
    const float* Wg3  = (const float*)d_in[14];
    const float* bg3  = (const float*)d_in[15];
    const float* W_ih = (const float*)d_in[16];
    const float* W_hh = (const float*)d_in[17];
    const float* b_ih = (const float*)d_in[18];
    const float* b_hh = (const float*)d_in[19];
    const float* Wo1  = (const float*)d_in[20];
    const float* bo1  = (const float*)d_in[21];
    const float* Wo2  = (const float*)d_in[22];
    const float* bo2  = (const float*)d_in[23];
    float* out = (float*)d_out;

    float *pA, *pB, *pS2a, *pS2b;
    cudaGetSymbolAddress((void**)&pA,   g_A);
    cudaGetSymbolAddress((void**)&pB,   g_B);
    cudaGetSymbolAddress((void**)&pS2a, g_S2a);
    cudaGetSymbolAddress((void**)&pS2b, g_S2b);

    cudaFuncSetAttribute(pair_mma_kernel, cudaFuncAttributeMaxDynamicSharedMemorySize, PAIR_DYN_SMEM);

    dim3 blk(256);

    // Wf2 split + A/B projection (one launch)
    prep_ab_kernel<<<512, blk>>>(hid, Wf1, Wf2);

    // S2 halves: sum over i in [0,256) -> S2a, [256,512) -> S2b
    pair_mma_kernel<<<dim3(512, 2), blk, PAIR_DYN_SMEM>>>(pA, pB, bf1, bf2, pS2a, pS2b);

    // fused tail: summ -> g-MLP -> LSTM -> o-MLP (one launch)
    tail_kernel<<<128, blk>>>(x, h0, c0, Wf3, bf3, Wg1, bg1, Wg2, bg2, Wg3, bg3,
                              W_ih, W_hh, b_ih, b_hh, Wo1, bo1, Wo2, bo2, out);
}

// round 8
// speedup vs baseline: 1.0896x; 1.0896x over previous
#include <cuda_runtime.h>
#include <cuda_bf16.h>
#include <cstdint>

#define NN 512

// ---------------- scratch (no allocations allowed) ----------------
__device__ float g_A[NN * 256];
__device__ float g_B[NN * 256];
__device__ float g_S2a[NN * 256];
__device__ float g_S2b[NN * 256];
// Wf2 split into bf16 hi/lo, chunked layout [kc][n][64]
__device__ uint4 g_Whi4[8192];
__device__ uint4 g_Wlo4[8192];

// ================= helpers =================
__device__ __forceinline__ uint32_t smem_u32(const void* p) {
    uint32_t a;
    asm("{ .reg .u64 t; cvta.to.shared.u64 t, %1; cvt.u32.u64 %0, t; }" : "=r"(a) : "l"(p));
    return a;
}

__device__ __forceinline__ void ldsm4(uint32_t (&r)[4], uint32_t addr) {
    asm volatile("ldmatrix.sync.aligned.m8n8.x4.shared.b16 {%0,%1,%2,%3}, [%4];"
        : "=r"(r[0]), "=r"(r[1]), "=r"(r[2]), "=r"(r[3]) : "r"(addr));
}

__device__ __forceinline__ void mma16816(float (&d)[4], const uint32_t (&a)[4],
                                         uint32_t b0, uint32_t b1) {
    asm volatile(
        "mma.sync.aligned.m16n8k16.row.col.f32.bf16.bf16.f32 "
        "{%0,%1,%2,%3}, {%4,%5,%6,%7}, {%8,%9}, {%0,%1,%2,%3};"
        : "+f"(d[0]), "+f"(d[1]), "+f"(d[2]), "+f"(d[3])
        : "r"(a[0]), "r"(a[1]), "r"(a[2]), "r"(a[3]), "r"(b0), "r"(b1));
}

__device__ __forceinline__ uint32_t pack_rn2(float f0, float f1) {
    uint32_t r; asm("cvt.rn.bf16x2.f32 %0, %1, %2;" : "=r"(r) : "f"(f1), "f"(f0));
    return r;
}

#define CP_ASYNC16(dst, src) \
    asm volatile("cp.async.cg.shared.global [%0], [%1], 16;" :: "r"(dst), "l"(src))
#define CP_COMMIT() asm volatile("cp.async.commit_group;" ::: "memory")
#define CP_WAIT0()  asm volatile("cp.async.wait_group 0;"  ::: "memory")

// ================= pair kernel smem layout (byte offsets) =================
// W hi/lo double-buffered; split A hi/lo double-buffered; raw A single.
#define OFF_WHI 0u         // 2 x 32768
#define OFF_WLO 65536u     // 2 x 32768
#define OFF_AHI 131072u    // 2 x 16384 (split hi, swizzled)
#define OFF_ALO 163840u    // 2 x 16384
#define OFF_RAW 196608u    // 1 x 32768 (raw A fp32)
#define OFF_BB  229376u    // 1024
#define OFF_B2  230400u    // 1024
#define PAIR_DYN_SMEM (231424u + 128u)

// ---------------- pairwise HMMA kernel ----------------
// grid (512, 2): j = blockIdx.x, half = blockIdx.y (i-rows [half*256, half*256+256))
// S2half[j,n] = sum_{i in half} relu( relu(A[i]+B[j]+bf1) @ Wf2^T + bf2 )[n]
// 3-pass bf16 hi/lo split, fp32 accumulate. 1 sync/chunk (split double-buffered).
__global__ __launch_bounds__(256, 1) void pair_mma_kernel(
    const float* __restrict__ A, const float* __restrict__ Bm,
    const float* __restrict__ bf1, const float* __restrict__ bf2,
    float* __restrict__ S2a, float* __restrict__ S2b)
{
    extern __shared__ __align__(16) char smraw[];
    const uint32_t raw0 = smem_u32(smraw);
    const uint32_t sb = (raw0 + 127u) & ~127u;
    char* smp = smraw + (sb - raw0);

    const int j = blockIdx.x;
    const int half = blockIdx.y;
    const int t = threadIdx.x;
    const int lane = t & 31;
    const int w = t >> 5;
    const int wm = w >> 2;
    const int wn = w & 3;

    float* sBB = (float*)(smp + OFF_BB);
    float* sB2 = (float*)(smp + OFF_B2);

    sBB[t] = Bm[j * 256 + t] + bf1[t];
    sB2[t] = bf2[t];

    const uint32_t lx = (uint32_t)(lane & 7) * 16u;
    const uint32_t rowOff = (uint32_t)(lane & 15) * 128u;
    const uint32_t segOff = (uint32_t)(lane >> 4) * 16u;
    const uint32_t wmOff = (uint32_t)(wm * 64) * 128u + rowOff;
    const uint32_t wnOff = (uint32_t)(wn * 64) * 128u + rowOff;

    float s[16];
#pragma unroll
    for (int q = 0; q < 16; q++) s[q] = 0.f;

    float acc[4][8][4];
#pragma unroll
    for (int mt = 0; mt < 4; mt++)
#pragma unroll
        for (int nt = 0; nt < 8; nt++)
#pragma unroll
            for (int e = 0; e < 4; e++) acc[mt][nt][e] = 0.f;

#define STAGE_W_ASYNC(kc_, wb_) do { \
        const uint32_t wHiA = sb + OFF_WHI + (uint32_t)(wb_) * 32768u; \
        const uint32_t wLoA = sb + OFF_WLO + (uint32_t)(wb_) * 32768u; \
        const uint4* srcH = g_Whi4 + (kc_) * 2048; \
        const uint4* srcL = g_Wlo4 + (kc_) * 2048; \
        _Pragma("unroll") \
        for (int r = 0; r < 8; r++) { \
            const int li = r * 256 + t; \
            const int n_ = li >> 3, seg_ = li & 7; \
            const uint32_t sw = ((uint32_t)(n_ * 128 + seg_ * 16)) ^ ((uint32_t)(n_ & 7) * 16u); \
            CP_ASYNC16(wHiA + sw, (const void*)(srcH + li)); \
            CP_ASYNC16(wLoA + sw, (const void*)(srcL + li)); \
        } \
    } while (0)

#define STAGE_A_ASYNC(it_, kc_) do { \
        const uint32_t rawA = sb + OFF_RAW; \
        const float* srcA = A + ((it_) * 128) * 256 + (kc_) * 64; \
        _Pragma("unroll") \
        for (int r = 0; r < 8; r++) { \
            const int li = r * 256 + t; \
            const int row_ = li >> 4, seg_ = li & 15; \
            CP_ASYNC16(rawA + (uint32_t)li * 16u, (const void*)(srcA + row_ * 256 + seg_ * 4)); \
        } \
    } while (0)

#define CONVERT_A(kc_, db_) do { \
        const float* rawp = (const float*)(smp + OFF_RAW); \
        char* aHi = smp + OFF_AHI + (uint32_t)(db_) * 16384u; \
        char* aLo = smp + OFF_ALO + (uint32_t)(db_) * 16384u; \
        _Pragma("unroll") \
        for (int r = 0; r < 8; r++) { \
            const int li = r * 256 + t; \
            const int row_ = li >> 4, seg_ = li & 15; \
            float4 v = *(const float4*)(rawp + li * 4); \
            float4 bbv = *(const float4*)(sBB + (kc_) * 64 + seg_ * 4); \
            float f0 = fmaxf(v.x + bbv.x, 0.f), f1 = fmaxf(v.y + bbv.y, 0.f); \
            float f2 = fmaxf(v.z + bbv.z, 0.f), f3 = fmaxf(v.w + bbv.w, 0.f); \
            uint2 hp, lp; \
            hp.x = pack_rn2(f0, f1); hp.y = pack_rn2(f2, f3); \
            lp.x = pack_rn2(f0 - __uint_as_float(hp.x << 16), \
                            f1 - __uint_as_float(hp.x & 0xFFFF0000u)); \
            lp.y = pack_rn2(f2 - __uint_as_float(hp.y << 16), \
                            f3 - __uint_as_float(hp.y & 0xFFFF0000u)); \
            const uint32_t off_ = (uint32_t)(row_ * 128 + seg_ * 8); \
            const uint32_t sw = off_ ^ ((uint32_t)(row_ & 7) * 16u); \
            *(uint2*)(aHi + sw) = hp; \
            *(uint2*)(aLo + sw) = lp; \
        } \
    } while (0)

    // ---- prologue: stage chunk 0, convert into split[0]
    STAGE_W_ASYNC(0, 0);
    STAGE_A_ASYNC(half * 2, 0);
    CP_COMMIT();
    __syncthreads();           // sBB visible (convert reads it)
    CP_WAIT0();
    CONVERT_A(0, 0);
    __syncthreads();           // split[0] + W[0] ready

    // ---- main pipeline: 8 chunks (2 i-tiles x 4 k-chunks), 1 sync/chunk
#pragma unroll 1
    for (int c = 0; c < 8; c++) {
        const int b = c & 1;

        // prefetch chunk c+1: W -> W[b^1], raw A -> raw (single)
        if (c < 7) {
            STAGE_W_ASYNC((c + 1) & 3, b ^ 1);
            STAGE_A_ASYNC(half * 2 + ((c + 1) >> 2), (c + 1) & 3);
            CP_COMMIT();
        }

        // ---- MMA on split[b] + W[b]: 4 k-steps of 16, 3 passes (hh, lh, hl)
        {
            const uint32_t aRowHi = sb + OFF_AHI + (uint32_t)b * 16384u + wmOff;
            const uint32_t aRowLo = sb + OFF_ALO + (uint32_t)b * 16384u + wmOff;
            const uint32_t wRowHi = sb + OFF_WHI + (uint32_t)b * 32768u + wnOff;
            const uint32_t wRowLo = sb + OFF_WLO + (uint32_t)b * 32768u + wnOff;
#pragma unroll
            for (int ks = 0; ks < 4; ks++) {
                const uint32_t kx = ((uint32_t)(ks * 32) + segOff) ^ lx;
                uint32_t aH[4][4], aL[4][4], wf[4][4];
#pragma unroll
                for (int mt = 0; mt < 4; mt++) ldsm4(aH[mt], aRowHi + mt * 2048 + kx);
#pragma unroll
                for (int np = 0; np < 4; np++) ldsm4(wf[np], wRowHi + np * 2048 + kx);
#pragma unroll
                for (int mt = 0; mt < 4; mt++)
#pragma unroll
                    for (int np = 0; np < 4; np++) {
                        mma16816(acc[mt][2 * np],     aH[mt], wf[np][0], wf[np][2]);
                        mma16816(acc[mt][2 * np + 1], aH[mt], wf[np][1], wf[np][3]);
                    }
#pragma unroll
                for (int mt = 0; mt < 4; mt++) ldsm4(aL[mt], aRowLo + mt * 2048 + kx);
#pragma unroll
                for (int mt = 0; mt < 4; mt++)
#pragma unroll
                    for (int np = 0; np < 4; np++) {
                        mma16816(acc[mt][2 * np],     aL[mt], wf[np][0], wf[np][2]);
                        mma16816(acc[mt][2 * np + 1], aL[mt], wf[np][1], wf[np][3]);
                    }
#pragma unroll
                for (int np = 0; np < 4; np++) ldsm4(wf[np], wRowLo + np * 2048 + kx);
#pragma unroll
                for (int mt = 0; mt < 4; mt++)
#pragma unroll
                    for (int np = 0; np < 4; np++) {
                        mma16816(acc[mt][2 * np],     aH[mt], wf[np][0], wf[np][2]);
                        mma16816(acc[mt][2 * np + 1], aH[mt], wf[np][1], wf[np][3]);
                    }
            }
        }

        // ---- convert next chunk into split[b^1] (disjoint from split[b] just read)
        if (c < 7) {
            CP_WAIT0();
            CONVERT_A((c + 1) & 3, b ^ 1);
        }

        // ---- i-tile boundary: fold relu(h2 + bf2) into running sums
        if ((c & 3) == 3) {
#pragma unroll
            for (int nt = 0; nt < 8; nt++) {
                const int col = wn * 64 + nt * 8 + (lane & 3) * 2;
                const float b20 = sB2[col], b21 = sB2[col + 1];
                float t0 = 0.f, t1 = 0.f;
#pragma unroll
                for (int mt = 0; mt < 4; mt++) {
                    t0 += fmaxf(acc[mt][nt][0] + b20, 0.f) + fmaxf(acc[mt][nt][2] + b20, 0.f);
                    t1 += fmaxf(acc[mt][nt][1] + b21, 0.f) + fmaxf(acc[mt][nt][3] + b21, 0.f);
                    acc[mt][nt][0] = 0.f; acc[mt][nt][1] = 0.f;
                    acc[mt][nt][2] = 0.f; acc[mt][nt][3] = 0.f;
                }
                s[nt * 2]     += t0;
                s[nt * 2 + 1] += t1;
            }
        }

        __syncthreads();   // one barrier per chunk
    }

#pragma unroll
    for (int q = 0; q < 16; q++) {
        s[q] += __shfl_xor_sync(0xFFFFFFFFu, s[q], 4);
        s[q] += __shfl_xor_sync(0xFFFFFFFFu, s[q], 8);
        s[q] += __shfl_xor_sync(0xFFFFFFFFu, s[q], 16);
    }
    float* sRED = (float*)(smp + OFF_RAW);   // alias raw buffer post-loop
    if (lane < 4) {
#pragma unroll
        for (int nt = 0; nt < 8; nt++) {
            const int col = wn * 64 + nt * 8 + lane * 2;
            sRED[wm * 256 + col]     = s[nt * 2];
            sRED[wm * 256 + col + 1] = s[nt * 2 + 1];
        }
    }
    __syncthreads();
    float* dst = half ? S2b : S2a;
    dst[j * 256 + t] = sRED[t] + sRED[256 + t];
}

// ---------------- fused prep: Wf2 split (bid<256) + A/B projection (bid>=256) ----------------
__global__ __launch_bounds__(256) void prep_ab_kernel(
    const float* __restrict__ hid, const float* __restrict__ Wf1,
    const float* __restrict__ Wf2)
{
    __shared__ float sX[32][34];
    __shared__ float sW[32][34];
    const int bid = blockIdx.x;
    const int t = threadIdx.x;

    if (bid < 256) {
        const int idx = bid * 256 + t;
        const int n = idx >> 8, k = idx & 255;
        const float v = Wf2[idx];
        const __nv_bfloat16 hb = __float2bfloat16(v);
        const float lf = v - __bfloat162float(hb);
        const int o = (k >> 6) * 16384 + n * 64 + (k & 63);
        ((__nv_bfloat16*)g_Whi4)[o] = hb;
        ((__nv_bfloat16*)g_Wlo4)[o] = __float2bfloat16(lf);
        return;
    }

    const int b = bid - 256;
    const int z = b >> 7;
    const int rem = b & 127;
    const int m0 = (rem >> 3) * 32;
    const int n0 = (rem & 7) * 32;
    const float* W = Wf1 + z * 128;
    float* C = z ? g_B : g_A;

    const int lm = t >> 3;
    const int lk = (t & 7) * 4;
    const int tm = (t >> 4) * 2;
    const int tn = (t & 15) * 2;

    float a00 = 0.f, a01 = 0.f, a10 = 0.f, a11 = 0.f;
    float4 xv = *(const float4*)(hid + (m0 + lm) * 128 + lk);
    float4 wv = *(const float4*)(W + (n0 + lm) * 256 + lk);

    for (int c = 0; c < 4; c++) {
        __syncthreads();
        sX[lk + 0][lm] = xv.x; sX[lk + 1][lm] = xv.y;
        sX[lk + 2][lm] = xv.z; sX[lk + 3][lm] = xv.w;
        sW[lk + 0][lm] = wv.x; sW[lk + 1][lm] = wv.y;
        sW[lk + 2][lm] = wv.z; sW[lk + 3][lm] = wv.w;
        __syncthreads();
        if (c < 3) {
            const int ko = (c + 1) * 32 + lk;
            xv = *(const float4*)(hid + (m0 + lm) * 128 + ko);
            wv = *(const float4*)(W + (n0 + lm) * 256 + ko);
        }
#pragma unroll
        for (int kk = 0; kk < 32; kk++) {
            float2 avv = *(const float2*)&sX[kk][tm];
            float2 bvv = *(const float2*)&sW[kk][tn];
            a00 = fmaf(avv.x, bvv.x, a00);
            a01 = fmaf(avv.x, bvv.y, a01);
            a10 = fmaf(avv.y, bvv.x, a10);
            a11 = fmaf(avv.y, bvv.y, a11);
        }
    }
    const int m = m0 + tm, n = n0 + tn;
    C[m * 256 + n] = a00;       C[m * 256 + n + 1] = a01;
    C[(m + 1) * 256 + n] = a10; C[(m + 1) * 256 + n + 1] = a11;
}

// ---------------- fused tail: coalesced warp-split layers ----------------
// 128 CTAs x 4 rows. lane = ng*8+kl; warp computes 4 outputs/iteration:
// n = it*32 + w*4 + ng; lane kl covers k = kl*4 + j*32 (coalesced W loads).
template<int K, int N, int ACT>
__device__ __forceinline__ void wlayer(
    const float* __restrict__ Xs,   // smem: 4 rows, stride 512, K floats used
    const float* __restrict__ W,    // [N][K] row-major gmem
    const float* __restrict__ bias, float bscale,
    float* __restrict__ Ys,         // smem dst base (row stride 512)
    int w, int ng, int kl)
{
#pragma unroll
    for (int it = 0; it < N / 32; it++) {
        const int n = it * 32 + w * 4 + ng;
        const float* wr = W + n * K + kl * 4;
        float a0 = 0.f, a1 = 0.f, a2 = 0.f, a3 = 0.f;
#pragma unroll
        for (int jj = 0; jj < K / 32; jj++) {
            const int k = kl * 4 + jj * 32;
            const float4 wv = *(const float4*)(wr + jj * 32);
            const float4 x0 = *(const float4*)(Xs + 0 * 512 + k);
            const float4 x1 = *(const float4*)(Xs + 1 * 512 + k);
            const float4 x2 = *(const float4*)(Xs + 2 * 512 + k);
            const float4 x3 = *(const float4*)(Xs + 3 * 512 + k);
            a0 += wv.x * x0.x + wv.y * x0.y + wv.z * x0.z + wv.w * x0.w;
            a1 += wv.x * x1.x + wv.y * x1.y + wv.z * x1.z + wv.w * x1.w;
            a2 += wv.x * x2.x + wv.y * x2.y + wv.z * x2.z + wv.w * x2.w;
            a3 += wv.x * x3.x + wv.y * x3.y + wv.z * x3.z + wv.w * x3.w;
        }
#pragma unroll
        for (int m = 1; m < 8; m <<= 1) {
            a0 += __shfl_xor_sync(0xFFFFFFFFu, a0, m);
            a1 += __shfl_xor_sync(0xFFFFFFFFu, a1, m);
            a2 += __shfl_xor_sync(0xFFFFFFFFu, a2, m);
            a3 += __shfl_xor_sync(0xFFFFFFFFu, a3, m);
        }
        if (kl == 0) {
            const float bb = bscale * bias[n];
            float v0 = a0 + bb, v1 = a1 + bb, v2 = a2 + bb, v3 = a3 + bb;
            if (ACT) {
                v0 = fmaxf(v0, 0.f); v1 = fmaxf(v1, 0.f);
                v2 = fmaxf(v2, 0.f); v3 = fmaxf(v3, 0.f);
            }
            Ys[0 * 512 + n] = v0; Ys[1 * 512 + n] = v1;
            Ys[2 * 512 + n] = v2; Ys[3 * 512 + n] = v3;
        }
    }
}

// gates: N=512, x = [ig | h0] in Xs (256 wide); W_ih/W_hh each [512][128]
__device__ __forceinline__ void wlayer_gates(
    const float* __restrict__ Xs,
    const float* __restrict__ Wih, const float* __restrict__ Whh,
    const float* __restrict__ bih, const float* __restrict__ bhh,
    float* __restrict__ Ys, int w, int ng, int kl)
{
#pragma unroll
    for (int it = 0; it < 16; it++) {
        const int n = it * 32 + w * 4 + ng;
        float a0 = 0.f, a1 = 0.f, a2 = 0.f, a3 = 0.f;
#pragma unroll
        for (int jj = 0; jj < 8; jj++) {
            const int k = kl * 4 + jj * 32;         // 0..255 (x index)
            const int wk = k & 127;                 // 0..127 (weight col)
            const float* base = (jj < 4) ? Wih : Whh;
            const float4 wv = *(const float4*)(base + n * 128 + wk);
            const float4 x0 = *(const float4*)(Xs + 0 * 512 + k);
            const float4 x1 = *(const float4*)(Xs + 1 * 512 + k);
            const float4 x2 = *(const float4*)(Xs + 2 * 512 + k);
            const float4 x3 = *(const float4*)(Xs + 3 * 512 + k);
            a0 += wv.x * x0.x + wv.y * x0.y + wv.z * x0.z + wv.w * x0.w;
            a1 += wv.x * x1.x + wv.y * x1.y + wv.z * x1.z + wv.w * x1.w;
            a2 += wv.x * x2.x + wv.y * x2.y + wv.z * x2.z + wv.w * x2.w;
            a3 += wv.x * x3.x + wv.y * x3.y + wv.z * x3.z + wv.w * x3.w;
        }
#pragma unroll
        for (int m = 1; m < 8; m <<= 1) {
            a0 += __shfl_xor_sync(0xFFFFFFFFu, a0, m);
            a1 += __shfl_xor_sync(0xFFFFFFFFu, a1, m);
            a2 += __shfl_xor_sync(0xFFFFFFFFu, a2, m);
            a3 += __shfl_xor_sync(0xFFFFFFFFu, a3, m);
        }
        if (kl == 0) {
            const float bb = bih[n] + bhh[n];
            Ys[0 * 512 + n] = a0 + bb; Ys[1 * 512 + n] = a1 + bb;
            Ys[2 * 512 + n] = a2 + bb; Ys[3 * 512 + n] = a3 + bb;
        }
    }
}

__global__ __launch_bounds__(256) void tail_kernel(
    const float* __restrict__ x,   const float* __restrict__ h0,
    const float* __restrict__ c0,
    const float* __restrict__ Wf3, const float* __restrict__ bf3,
    const float* __restrict__ Wg1, const float* __restrict__ bg1,
    const float* __restrict__ Wg2, const float* __restrict__ bg2,
    const float* __restrict__ Wg3, const float* __restrict__ bg3,
    const float* __restrict__ W_ih, const float* __restrict__ W_hh,
    const float* __restrict__ b_ih, const float* __restrict__ b_hh,
    const float* __restrict__ Wo1, const float* __restrict__ bo1,
    const float* __restrict__ Wo2, const float* __restrict__ bo2,
    float* __restrict__ out)
{
    __shared__ float Xa[4 * 512];
    __shared__ float Xb[4 * 512];
    const int t = threadIdx.x;
    const int w = t >> 5, lane = t & 31;
    const int ng = lane >> 3, kl = lane & 7;
    const int r0 = blockIdx.x * 4;

    // s0: Xa <- S2a + S2b
#pragma unroll
    for (int r = 0; r < 4; r++)
        Xa[r * 512 + t] = g_S2a[(r0 + r) * 256 + t] + g_S2b[(r0 + r) * 256 + t];
    __syncthreads();

    // s1: Xb[.][0..127] <- x rows; Xb[.][128..255] <- summ = Xa @ Wf3^T + 512*bf3
#pragma unroll
    for (int q = 0; q < 2; q++) {
        const int item = q * 256 + t;
        const int r = item >> 7, k = item & 127;
        Xb[r * 512 + k] = x[(r0 + r) * 128 + k];
    }
    wlayer<256, 128, 0>(Xa, Wf3, bf3, 512.f, Xb + 128, w, ng, kl);
    __syncthreads();

    // s2: Xa <- g1 = relu(Xb @ Wg1^T + bg1)
    wlayer<256, 256, 1>(Xb, Wg1, bg1, 1.f, Xa, w, ng, kl);
    __syncthreads();

    // s3: Xb <- g2 = relu(Xa @ Wg2^T + bg2)
    wlayer<256, 256, 1>(Xa, Wg2, bg2, 1.f, Xb, w, ng, kl);
    __syncthreads();

    // s4: Xa[.][0..127] <- ig = Xb @ Wg3^T + bg3; Xa[.][128..255] <- h0 rows
#pragma unroll
    for (int q = 0; q < 2; q++) {
        const int item = q * 256 + t;
        const int r = item >> 7, k = item & 127;
        Xa[r * 512 + 128 + k] = h0[(r0 + r) * 128 + k];
    }
    wlayer<256, 128, 0>(Xb, Wg3, bg3, 1.f, Xa, w, ng, kl);
    __syncthreads();

    // s5: Xb <- gates (512) = ig@W_ih^T + h0@W_hh^T + b_ih + b_hh
    wlayer_gates(Xa, W_ih, W_hh, b_ih, b_hh, Xb, w, ng, kl);
    __syncthreads();

    // s6: LSTM elementwise; hn -> Xa[.][0..127] + gmem; c -> gmem
#pragma unroll
    for (int q = 0; q < 2; q++) {
        const int item = q * 256 + t;
        const int r = item >> 7, h = item & 127;
        const float* g = Xb + r * 512;
        const float ig = 1.f / (1.f + expf(-g[h]));
        const float fg = 1.f / (1.f + expf(-g[128 + h]));
        const float gg = tanhf(g[256 + h]);
        const float og = 1.f / (1.f + expf(-g[384 + h]));
        const int gi = (r0 + r) * 128 + h;
        const float c = fg * c0[gi] + ig * gg;
        const float hn = og * tanhf(c);
        Xa[r * 512 + h] = hn;
        out[32768 + gi]  = hn;
        out[98304 + gi]  = hn;
        out[163840 + gi] = c;
    }
    __syncthreads();

    // s7: Xb <- o1 = relu(hn @ Wo1^T + bo1)  (K=128)
    wlayer<128, 256, 1>(Xa, Wo1, bo1, 1.f, Xb, w, ng, kl);
    __syncthreads();

    // s8: out = o1 @ Wo2^T + bo2  (N=64) -> gmem
#pragma unroll
    for (int it = 0; it < 2; it++) {
        const int n = it * 32 + w * 4 + ng;
        const float* wr = Wo2 + n * 256 + kl * 4;
        float a0 = 0.f, a1 = 0.f, a2 = 0.f, a3 = 0.f;
#pragma unroll
        for (int jj = 0; jj < 8; jj++) {
            const int k = kl * 4 + jj * 32;
            const float4 wv = *(const float4*)(wr + jj * 32);
            const float4 x0 = *(const float4*)(Xb + 0 * 512 + k);
            const float4 x1 = *(const float4*)(Xb + 1 * 512 + k);
            const float4 x2 = *(const float4*)(Xb + 2 * 512 + k);
            const float4 x3 = *(const float4*)(Xb + 3 * 512 + k);
            a0 += wv.x * x0.x + wv.y * x0.y + wv.z * x0.z + wv.w * x0.w;
            a1 += wv.x * x1.x + wv.y * x1.y + wv.z * x1.z + wv.w * x1.w;
            a2 += wv.x * x2.x + wv.y * x2.y + wv.z * x2.z + wv.w * x2.w;
            a3 += wv.x * x3.x + wv.y * x3.y + wv.z * x3.z + wv.w * x3.w;
        }
#pragma unroll
        for (int m = 1; m < 8; m <<= 1) {
            a0 += __shfl_xor_sync(0xFFFFFFFFu, a0, m);
            a1 += __shfl_xor_sync(0xFFFFFFFFu, a1, m);
            a2 += __shfl_xor_sync(0xFFFFFFFFu, a2, m);
            a3 += __shfl_xor_sync(0xFFFFFFFFu, a3, m);
        }
        if (kl == 0) {
            const float bb = bo2[n];
            out[(r0 + 0) * 64 + n] = a0 + bb;
            out[(r0 + 1) * 64 + n] = a1 + bb;
            out[(r0 + 2) * 64 + n] = a2 + bb;
            out[(r0 + 3) * 64 + n] = a3 + bb;
        }
    }
}

// ---------------- launch ----------------
extern "C" void kernel_launch(void* const* d_in, const int* in_sizes, int n_in,
                              void* d_out, int out_size)
{
    const float* x    = (const float*)d_in[0];
    const float* hid  = (const float*)d_in[1];
    const float* h0   = (const float*)d_in[2];
    const float* c0   = (const float*)d_in[3];
    const float* Wf1  = (const float*)d_in[4];
    const float* bf1  = (const float*)d_in[5];
    const float* Wf2  = (const float*)d_in[6];
    const float* bf2  = (const float*)d_in[7];
    const float* Wf3  = (const float*)d_in[8];
    const float* bf3  = (const float*)d_in[9];
    const float* Wg1  = (const float*)d_in[10];
    const float* bg1  = (const float*)d_in[11];
    const float* Wg2  = (const float*)d_in[12];
    const float* bg2  = (const float*)d_in[13];
    const float* Wg3  = (const float*)d_in[14];
    const float* bg3  = (const float*)d_in[15];
    const float* W_ih = (const float*)d_in[16];
    const float* W_hh = (const float*)d_in[17];
    const float* b_ih = (const float*)d_in[18];
    const float* b_hh = (const float*)d_in[19];
    const float* Wo1  = (const float*)d_in[20];
    const float* bo1  = (const float*)d_in[21];
    const float* Wo2  = (const float*)d_in[22];
    const float* bo2  = (const float*)d_in[23];
    float* out = (float*)d_out;

    float *pA, *pB, *pS2a, *pS2b;
    cudaGetSymbolAddress((void**)&pA,   g_A);
    cudaGetSymbolAddress((void**)&pB,   g_B);
    cudaGetSymbolAddress((void**)&pS2a, g_S2a);
    cudaGetSymbolAddress((void**)&pS2b, g_S2b);

    cudaFuncSetAttribute(pair_mma_kernel, cudaFuncAttributeMaxDynamicSharedMemorySize, PAIR_DYN_SMEM);

    dim3 blk(256);

    // Wf2 split + A/B projection (one launch)
    prep_ab_kernel<<<512, blk>>>(hid, Wf1, Wf2);

    // S2 halves: sum over i in [0,256) -> S2a, [256,512) -> S2b
    pair_mma_kernel<<<dim3(512, 2), blk, PAIR_DYN_SMEM>>>(pA, pB, bf1, bf2, pS2a, pS2b);

    // fused tail (coalesced warp-split)
    tail_kernel<<<128, blk>>>(x, h0, c0, Wf3, bf3, Wg1, bg1, Wg2, bg2, Wg3, bg3,
                              W_ih, W_hh, b_ih, b_hh, Wo1, bo1, Wo2, bo2, out);
}